// round 12
// baseline (speedup 1.0000x reference)
#include <cuda_runtime.h>

#define N_  2048
#define L_  2
#define H_  4
#define D_  16
#define F_  64
#define E_  64
#define C_  32
#define NL_ (N_*L_)             // 4096
#define NLH (N_*L_*H_)          // 16384
#define EPS 1e-5f

#define ET  512                 // epilogue threads
#define EK  (NL_/ET)            // 8 j's per thread
#define EW  (ET/32)             // 16 warps

#define PF  4                   // ffn prefetch ring depth (16 loads in flight)

// Scratch (device globals — no allocation allowed)
__device__ float g_logits[NLH];            // 64 KB
__device__ float g_value [NLH * D_];       // 1 MB
__device__ float g_attn_scratch[C_ * NLH]; // 2 MB fallback if attn not in d_out
__device__ int   g_comp[N_];               // normalized int32 component ids

// ---------------------------------------------------------------------------
__device__ __forceinline__ float warp_sum16(float v) {
    v += __shfl_xor_sync(0xffffffffu, v, 1);
    v += __shfl_xor_sync(0xffffffffu, v, 2);
    v += __shfl_xor_sync(0xffffffffu, v, 4);
    v += __shfl_xor_sync(0xffffffffu, v, 8);
    return v;
}

__device__ __forceinline__ float warp_sum32(float v) {
    v += __shfl_xor_sync(0xffffffffu, v, 16);
    return warp_sum16(v);
}

__device__ __forceinline__ float warp_max32(float v) {
    v = fmaxf(v, __shfl_xor_sync(0xffffffffu, v, 16));
    v = fmaxf(v, __shfl_xor_sync(0xffffffffu, v, 8));
    v = fmaxf(v, __shfl_xor_sync(0xffffffffu, v, 4));
    v = fmaxf(v, __shfl_xor_sync(0xffffffffu, v, 2));
    v = fmaxf(v, __shfl_xor_sync(0xffffffffu, v, 1));
    return v;
}

__device__ __forceinline__ float dot4(float4 w, float4 f) {
    return fmaf(w.x, f.x, fmaf(w.y, f.y, fmaf(w.z, f.z, w.w * f.w)));
}

// ---------------------------------------------------------------------------
// Kernel 1: per-node FFNs, key + value paths interleaved. One warp per (n,l,h).
// Explicit PF-deep prefetch ring: loads for step s+PF issue BEFORE step s's
// shuffle chains -> >= 4*PF independent LDGs in flight per warp, guaranteed.
// Blocks 0..15 additionally normalize component ids into g_comp (dtype
// auto-detected); hidden in the launch tail.
// ---------------------------------------------------------------------------
__global__ __launch_bounds__(128) void ffn_kernel(
    const float* __restrict__ feat,  const float* __restrict__ query,
    const float* __restrict__ kw0,   const float* __restrict__ kb0,
    const float* __restrict__ kw1,   const float* __restrict__ kb1,
    const float* __restrict__ vw0,   const float* __restrict__ vb0,
    const float* __restrict__ vw1,   const float* __restrict__ vb1,
    const float* __restrict__ key_gamma, const float* __restrict__ key_beta,
    const int* __restrict__ comp)
{
    const int nl   = blockIdx.x;
    const int wid  = threadIdx.x >> 5;
    const int lane = threadIdx.x & 31;
    const int l16  = lane & 15;
    const int half = lane >> 4;
    const int nlh  = nl * H_ + wid;

    const float4 f4 = ((const float4*)(feat + (size_t)nl * E_))[l16];
    const float gd = key_gamma[l16];
    const float bd = key_beta [l16];

    const size_t o0 = (size_t)nlh * (F_ * E_);
    const size_t o1 = (size_t)nlh * (F_ * D_);
    const size_t ob = (size_t)nlh * F_;
    const size_t od = (size_t)nlh * D_;

    const float* kw0p = kw0 + o0 + half * E_ + l16 * 4;
    const float* vw0p = vw0 + o0 + half * E_ + l16 * 4;
    const float* kw1p = kw1 + o1 + half * D_ + l16;
    const float* vw1p = vw1 + o1 + half * D_ + l16;

    const float kb0a = kb0[ob + lane],      kb0b = kb0[ob + 32 + lane];
    const float vb0a = vb0[ob + lane],      vb0b = vb0[ob + 32 + lane];

    // ---- prefetch ring: fill PF steps ----
    float4 wkb[PF], wvb[PF];
    float  w1kb[PF], w1vb[PF];
#pragma unroll
    for (int i = 0; i < PF; i++) {
        wkb [i] = __ldcs((const float4*)(kw0p + i * 2 * E_));
        wvb [i] = __ldcs((const float4*)(vw0p + i * 2 * E_));
        w1kb[i] = __ldcs(kw1p + i * 2 * D_);
        w1vb[i] = __ldcs(vw1p + i * 2 * D_);
    }

    float accK = 0.f, accV = 0.f;
#pragma unroll
    for (int s = 0; s < 32; s++) {
        const int slot = s & (PF - 1);
        float4 wk = wkb[slot],  wv = wvb[slot];
        float w1k = w1kb[slot], w1v = w1vb[slot];

        // issue next loads BEFORE the dependent shuffle chains
        if (s + PF < 32) {
            wkb [slot] = __ldcs((const float4*)(kw0p + (s + PF) * 2 * E_));
            wvb [slot] = __ldcs((const float4*)(vw0p + (s + PF) * 2 * E_));
            w1kb[slot] = __ldcs(kw1p + (s + PF) * 2 * D_);
            w1vb[slot] = __ldcs(vw1p + (s + PF) * 2 * D_);
        }

        float tk = warp_sum16(dot4(wk, f4));   // two independent shfl chains
        float tv = warp_sum16(dot4(wv, f4));

        float bK = __shfl_sync(0xffffffffu, (s < 16) ? kb0a : kb0b, 2*s + half);
        float bV = __shfl_sync(0xffffffffu, (s < 16) ? vb0a : vb0b, 2*s + half);

        accK = fmaf(fmaxf(tk + bK, 0.f), w1k, accK);
        accV = fmaf(fmaxf(tv + bV, 0.f), w1v, accV);
    }

    float xK = accK + __shfl_xor_sync(0xffffffffu, accK, 16) + kb1[od + l16];
    float xV = accV + __shfl_xor_sync(0xffffffffu, accV, 16) + vb1[od + l16];

    // LayerNorm over 16 d-values (both halves replicated); ref reuses key LN
    float muK  = warp_sum16(xK) * (1.f/16.f);
    float dlK  = xK - muK;
    float varK = warp_sum16(dlK * dlK) * (1.f/16.f);
    float kln  = fmaf(dlK * rsqrtf(varK + EPS), gd, bd);

    float muV  = warp_sum16(xV) * (1.f/16.f);
    float dlV  = xV - muV;
    float varV = warp_sum16(dlV * dlV) * (1.f/16.f);
    float vln  = fmaf(dlV * rsqrtf(varV + EPS), gd, bd);

    float p = warp_sum16(kln * query[od + l16]);
    if (lane == 0) g_logits[nlh] = p;
    if (lane < D_) g_value[od + lane] = vln;

    // ---- comp normalization (blocks 0..15, 128 nodes each) ----
    if (blockIdx.x < 16) {
        __shared__ int s_nz;
        if (threadIdx.x == 0) s_nz = 0;
        __syncthreads();
        // dtype: int64 iff all odd 32-bit words in the first N_ words are 0
        int vz = 0;
        for (int i = threadIdx.x; i < N_/2; i += 128) vz |= comp[2*i + 1];
        if (__any_sync(0xffffffffu, vz != 0) && lane == 0) atomicOr(&s_nz, 1);
        __syncthreads();
        const int is64 = (s_nz == 0);
        const int n = blockIdx.x * 128 + threadIdx.x;
        g_comp[n] = is64 ? comp[2*n] : comp[n];
    }
}

// ---------------------------------------------------------------------------
// Kernel 2 (fused epilogue): one block per (c,h), 512 threads (R8 shape).
// Sparse masked attn writes (zeros laid down by the memset node).
// ---------------------------------------------------------------------------
__global__ __launch_bounds__(ET) void epilogue_kernel(
    const float* __restrict__ out_gamma, const float* __restrict__ out_beta,
    float* __restrict__ attn_base, float* __restrict__ out,
    float* __restrict__ uid_out, int write_uid)
{
    const int c = blockIdx.x >> 2;
    const int h = blockIdx.x & 3;
    const int t = threadIdx.x;
    const int wid  = t >> 5;
    const int lane = t & 31;

    __shared__ float swred[EW];
    __shared__ float sstat;           // reused: max, then rinv
    __shared__ float swacc[EW * 17];

    // ---- single pipelined sweep: logits + comp ids into registers ----
    float lg[EK];
    int   mk[EK];
#pragma unroll
    for (int k = 0; k < EK; k++) {
        int j = t + k * ET;
        lg[k] = g_logits[j * H_ + h];
        mk[k] = (g_comp[j >> 1] == c);
    }

    // ---- masked max ----
    float m = -3.0e38f;
#pragma unroll
    for (int k = 0; k < EK; k++) m = fmaxf(m, mk[k] ? lg[k] : -3.0e38f);
    m = warp_max32(m);
    if (lane == 0) swred[wid] = m;
    __syncthreads();
    if (t == 0) {
        float mm = swred[0];
#pragma unroll
        for (int w = 1; w < EW; w++) mm = fmaxf(mm, swred[w]);
        sstat = mm;
    }
    __syncthreads();
    const float mx = sstat;

    // ---- exp once, masked sum ----
    float e[EK];
    float ss = 0.f;
#pragma unroll
    for (int k = 0; k < EK; k++) {
        e[k] = mk[k] ? __expf(lg[k] - mx) : 0.f;
        ss += e[k];
    }
    ss = warp_sum32(ss);
    if (lane == 0) swred[wid] = ss;
    __syncthreads();
    if (t == 0) {
        float tot = 0.f;
#pragma unroll
        for (int w = 0; w < EW; w++) tot += swred[w];
        sstat = 1.f / tot;
    }
    __syncthreads();
    const float rinv = sstat;

    // ---- attn writes + weighted value accumulation (matches only) ----
    float* attn_c = attn_base + (size_t)c * NLH;
    float acc[D_];
#pragma unroll
    for (int d = 0; d < D_; d++) acc[d] = 0.f;

#pragma unroll
    for (int k = 0; k < EK; k++) {
        if (mk[k]) {
            int idx = (t + k * ET) * H_ + h;
            float w = e[k] * rinv;
            attn_c[idx] = w;
            const float4* v4 = (const float4*)(g_value + (size_t)idx * D_);
            float4 va = v4[0], vb = v4[1], vc = v4[2], vd = v4[3];
            acc[0]  = fmaf(w, va.x, acc[0]);  acc[1]  = fmaf(w, va.y, acc[1]);
            acc[2]  = fmaf(w, va.z, acc[2]);  acc[3]  = fmaf(w, va.w, acc[3]);
            acc[4]  = fmaf(w, vb.x, acc[4]);  acc[5]  = fmaf(w, vb.y, acc[5]);
            acc[6]  = fmaf(w, vb.z, acc[6]);  acc[7]  = fmaf(w, vb.w, acc[7]);
            acc[8]  = fmaf(w, vc.x, acc[8]);  acc[9]  = fmaf(w, vc.y, acc[9]);
            acc[10] = fmaf(w, vc.z, acc[10]); acc[11] = fmaf(w, vc.w, acc[11]);
            acc[12] = fmaf(w, vd.x, acc[12]); acc[13] = fmaf(w, vd.y, acc[13]);
            acc[14] = fmaf(w, vd.z, acc[14]); acc[15] = fmaf(w, vd.w, acc[15]);
        }
    }

    // ---- per-warp reduction, then block combine ----
#pragma unroll
    for (int d = 0; d < D_; d++) acc[d] = warp_sum32(acc[d]);
    if (lane < D_) swacc[wid * 17 + lane] = acc[lane];
    __syncthreads();

    // ---- combine EW warps + final LayerNorm over d (warp 0) ----
    if (t < 32) {
        int d = t & 15;
        float x = 0.f;
#pragma unroll
        for (int w = 0; w < EW; w++) x += swacc[w * 17 + d];
        float mu = warp_sum16(x) * (1.f/16.f);
        float dl = x - mu;
        float var = warp_sum16(dl * dl) * (1.f/16.f);
        if (t < 16)
            out[c * (H_*D_) + h * D_ + d] =
                fmaf(dl * rsqrtf(var + EPS), out_gamma[d], out_beta[d]);
    }

    if (write_uid && h == 0 && t == 0)
        uid_out[c] = (float)c;
}

// ---------------------------------------------------------------------------
extern "C" void kernel_launch(void* const* d_in, const int* in_sizes, int n_in,
                              void* d_out, int out_size) {
    const float* feat      = (const float*)d_in[0];
    const float* query     = (const float*)d_in[1];
    const float* kw0       = (const float*)d_in[2];
    const float* kb0       = (const float*)d_in[3];
    const float* kw1       = (const float*)d_in[4];
    const float* kb1       = (const float*)d_in[5];
    const float* vw0       = (const float*)d_in[6];
    const float* vb0       = (const float*)d_in[7];
    const float* vw1       = (const float*)d_in[8];
    const float* vb1       = (const float*)d_in[9];
    const float* key_gamma = (const float*)d_in[10];
    const float* key_beta  = (const float*)d_in[11];
    const float* out_gamma = (const float*)d_in[12];
    const float* out_beta  = (const float*)d_in[13];
    const int*   comp      = (const int*)  d_in[14];   // int32 or int64; detected on device

    float* out = (float*)d_out;

    const int SZ_OUT  = C_ * H_ * D_;      // 2048
    const int SZ_ATTN = C_ * NLH;          // 524288
    const int full_attn = (out_size >= SZ_OUT + SZ_ATTN) ? 1 : 0;
    const int full_uid  = (out_size >= SZ_OUT + SZ_ATTN + C_) ? 1 : 0;

    float* attn_base;
    if (full_attn) {
        attn_base = out + SZ_OUT;
    } else {
        void* p = nullptr;
        cudaGetSymbolAddress(&p, g_attn_scratch);
        attn_base = (float*)p;
    }
    // d_out is poisoned before timing; zero the (sparse) attn region.
    cudaMemsetAsync(attn_base, 0, (size_t)SZ_ATTN * sizeof(float), 0);

    ffn_kernel<<<N_ * L_, 128>>>(feat, query, kw0, kb0, kw1, kb1,
                                 vw0, vb0, vw1, vb1, key_gamma, key_beta, comp);

    float* uid_out = full_uid ? (out + SZ_OUT + SZ_ATTN) : (float*)nullptr;
    epilogue_kernel<<<C_ * H_, ET>>>(out_gamma, out_beta,
                                     attn_base, out, uid_out, full_uid);
}

// round 13
// speedup vs baseline: 1.0302x; 1.0302x over previous
#include <cuda_runtime.h>

#define N_  2048
#define L_  2
#define H_  4
#define D_  16
#define F_  64
#define E_  64
#define C_  32
#define NL_ (N_*L_)             // 4096
#define NLH (N_*L_*H_)          // 16384
#define EPS 1e-5f

#define ET  512                 // epilogue threads
#define EK  (NL_/ET)            // 8 j's per thread
#define EW  (ET/32)             // 16 warps

// Scratch (device globals — no allocation allowed)
__device__ float g_logits[NLH];            // 64 KB
__device__ float g_value [NLH * D_];       // 1 MB
__device__ float g_attn_scratch[C_ * NLH]; // 2 MB fallback if attn not in d_out
__device__ int   g_comp[N_];               // normalized int32 component ids

// ---------------------------------------------------------------------------
__device__ __forceinline__ float warp_sum16(float v) {
    v += __shfl_xor_sync(0xffffffffu, v, 1);
    v += __shfl_xor_sync(0xffffffffu, v, 2);
    v += __shfl_xor_sync(0xffffffffu, v, 4);
    v += __shfl_xor_sync(0xffffffffu, v, 8);
    return v;
}

__device__ __forceinline__ float warp_sum32(float v) {
    v += __shfl_xor_sync(0xffffffffu, v, 16);
    return warp_sum16(v);
}

__device__ __forceinline__ float warp_max32(float v) {
    v = fmaxf(v, __shfl_xor_sync(0xffffffffu, v, 16));
    v = fmaxf(v, __shfl_xor_sync(0xffffffffu, v, 8));
    v = fmaxf(v, __shfl_xor_sync(0xffffffffu, v, 4));
    v = fmaxf(v, __shfl_xor_sync(0xffffffffu, v, 2));
    v = fmaxf(v, __shfl_xor_sync(0xffffffffu, v, 1));
    return v;
}

__device__ __forceinline__ float dot4(float4 w, float4 f) {
    return fmaf(w.x, f.x, fmaf(w.y, f.y, fmaf(w.z, f.z, w.w * f.w)));
}

// ---------------------------------------------------------------------------
// Kernel 1: per-node FFNs, ONE PATH (key or value) per block — grid 2*N*L.
// path = blockIdx.x & 1 (0 = key -> logits, 1 = value -> g_value).
// One warp per head. Per step: one LDG.128 across warp = 512B contiguous
// (w0, two rows), one LDG.32 across warp = one 128B line (w1, two rows).
// Halved per-CTA duration -> halved wave-tail spread; lower regs -> more
// resident CTAs/SM. Blocks 0..15 also normalize component ids into g_comp.
// ---------------------------------------------------------------------------
__global__ __launch_bounds__(128) void ffn_kernel(
    const float* __restrict__ feat,  const float* __restrict__ query,
    const float* __restrict__ kw0,   const float* __restrict__ kb0,
    const float* __restrict__ kw1,   const float* __restrict__ kb1,
    const float* __restrict__ vw0,   const float* __restrict__ vb0,
    const float* __restrict__ vw1,   const float* __restrict__ vb1,
    const float* __restrict__ key_gamma, const float* __restrict__ key_beta,
    const int* __restrict__ comp)
{
    const int bid  = blockIdx.x;
    const int nl   = bid >> 1;
    const int path = bid & 1;
    const int wid  = threadIdx.x >> 5;
    const int lane = threadIdx.x & 31;
    const int l16  = lane & 15;
    const int half = lane >> 4;
    const int nlh  = nl * H_ + wid;

    const float* w0 = path ? vw0 : kw0;
    const float* b0 = path ? vb0 : kb0;
    const float* w1 = path ? vw1 : kw1;
    const float* b1 = path ? vb1 : kb1;

    const float4 f4 = ((const float4*)(feat + (size_t)nl * E_))[l16];
    const float gd = key_gamma[l16];   // ref reuses key LN for both paths
    const float bd = key_beta [l16];

    const size_t o0 = (size_t)nlh * (F_ * E_);
    const size_t o1 = (size_t)nlh * (F_ * D_);
    const size_t ob = (size_t)nlh * F_;
    const size_t od = (size_t)nlh * D_;

    const float* w0p = w0 + o0 + half * E_ + l16 * 4;
    const float* w1p = w1 + o1 + half * D_ + l16;

    const float b0a = b0[ob + lane];        // f = 0..31
    const float b0b = b0[ob + 32 + lane];   // f = 32..63

    float acc = 0.f;
#pragma unroll
    for (int s = 0; s < 32; s++) {
        float4 w  = __ldcs((const float4*)(w0p + s * 2 * E_));
        float w1v = __ldcs(w1p + s * 2 * D_);

        float t = warp_sum16(dot4(w, f4));  // dot(feat, w0[f,:]) in half's lanes
        float b = __shfl_sync(0xffffffffu, (s < 16) ? b0a : b0b, 2*s + half);
        acc = fmaf(fmaxf(t + b, 0.f), w1v, acc);
    }

    // combine even-f (lanes 0-15) and odd-f (lanes 16-31) partials
    float x = acc + __shfl_xor_sync(0xffffffffu, acc, 16) + b1[od + l16];

    // LayerNorm over the 16 d-values (replicated in both halves)
    float mu  = warp_sum16(x) * (1.f/16.f);
    float dl  = x - mu;
    float var = warp_sum16(dl * dl) * (1.f/16.f);
    float ln  = fmaf(dl * rsqrtf(var + EPS), gd, bd);

    if (path == 0) {
        float p = warp_sum16(ln * query[od + l16]);
        if (lane == 0) g_logits[nlh] = p;
    } else {
        if (lane < D_) g_value[od + lane] = ln;
    }

    // ---- comp normalization (blocks 0..15, 128 nodes each) ----
    if (bid < 16) {
        __shared__ int s_nz;
        if (threadIdx.x == 0) s_nz = 0;
        __syncthreads();
        // dtype: int64 iff all odd 32-bit words in the first N_ words are 0
        int vz = 0;
        for (int i = threadIdx.x; i < N_/2; i += 128) vz |= comp[2*i + 1];
        if (__any_sync(0xffffffffu, vz != 0) && lane == 0) atomicOr(&s_nz, 1);
        __syncthreads();
        const int is64 = (s_nz == 0);
        const int n = bid * 128 + threadIdx.x;
        g_comp[n] = is64 ? comp[2*n] : comp[n];
    }
}

// ---------------------------------------------------------------------------
// Kernel 2 (fused epilogue): one block per (c,h), 512 threads (R8 shape).
// Sparse masked attn writes (zeros laid down by the memset node).
// ---------------------------------------------------------------------------
__global__ __launch_bounds__(ET) void epilogue_kernel(
    const float* __restrict__ out_gamma, const float* __restrict__ out_beta,
    float* __restrict__ attn_base, float* __restrict__ out,
    float* __restrict__ uid_out, int write_uid)
{
    const int c = blockIdx.x >> 2;
    const int h = blockIdx.x & 3;
    const int t = threadIdx.x;
    const int wid  = t >> 5;
    const int lane = t & 31;

    __shared__ float swred[EW];
    __shared__ float sstat;           // reused: max, then rinv
    __shared__ float swacc[EW * 17];

    // ---- single pipelined sweep: logits + comp ids into registers ----
    float lg[EK];
    int   mk[EK];
#pragma unroll
    for (int k = 0; k < EK; k++) {
        int j = t + k * ET;
        lg[k] = g_logits[j * H_ + h];
        mk[k] = (g_comp[j >> 1] == c);
    }

    // ---- masked max ----
    float m = -3.0e38f;
#pragma unroll
    for (int k = 0; k < EK; k++) m = fmaxf(m, mk[k] ? lg[k] : -3.0e38f);
    m = warp_max32(m);
    if (lane == 0) swred[wid] = m;
    __syncthreads();
    if (t == 0) {
        float mm = swred[0];
#pragma unroll
        for (int w = 1; w < EW; w++) mm = fmaxf(mm, swred[w]);
        sstat = mm;
    }
    __syncthreads();
    const float mx = sstat;

    // ---- exp once, masked sum ----
    float e[EK];
    float ss = 0.f;
#pragma unroll
    for (int k = 0; k < EK; k++) {
        e[k] = mk[k] ? __expf(lg[k] - mx) : 0.f;
        ss += e[k];
    }
    ss = warp_sum32(ss);
    if (lane == 0) swred[wid] = ss;
    __syncthreads();
    if (t == 0) {
        float tot = 0.f;
#pragma unroll
        for (int w = 0; w < EW; w++) tot += swred[w];
        sstat = 1.f / tot;
    }
    __syncthreads();
    const float rinv = sstat;

    // ---- attn writes + weighted value accumulation (matches only) ----
    float* attn_c = attn_base + (size_t)c * NLH;
    float acc[D_];
#pragma unroll
    for (int d = 0; d < D_; d++) acc[d] = 0.f;

#pragma unroll
    for (int k = 0; k < EK; k++) {
        if (mk[k]) {
            int idx = (t + k * ET) * H_ + h;
            float w = e[k] * rinv;
            attn_c[idx] = w;
            const float4* v4 = (const float4*)(g_value + (size_t)idx * D_);
            float4 va = v4[0], vb = v4[1], vc = v4[2], vd = v4[3];
            acc[0]  = fmaf(w, va.x, acc[0]);  acc[1]  = fmaf(w, va.y, acc[1]);
            acc[2]  = fmaf(w, va.z, acc[2]);  acc[3]  = fmaf(w, va.w, acc[3]);
            acc[4]  = fmaf(w, vb.x, acc[4]);  acc[5]  = fmaf(w, vb.y, acc[5]);
            acc[6]  = fmaf(w, vb.z, acc[6]);  acc[7]  = fmaf(w, vb.w, acc[7]);
            acc[8]  = fmaf(w, vc.x, acc[8]);  acc[9]  = fmaf(w, vc.y, acc[9]);
            acc[10] = fmaf(w, vc.z, acc[10]); acc[11] = fmaf(w, vc.w, acc[11]);
            acc[12] = fmaf(w, vd.x, acc[12]); acc[13] = fmaf(w, vd.y, acc[13]);
            acc[14] = fmaf(w, vd.z, acc[14]); acc[15] = fmaf(w, vd.w, acc[15]);
        }
    }

    // ---- per-warp reduction, then block combine ----
#pragma unroll
    for (int d = 0; d < D_; d++) acc[d] = warp_sum32(acc[d]);
    if (lane < D_) swacc[wid * 17 + lane] = acc[lane];
    __syncthreads();

    // ---- combine EW warps + final LayerNorm over d (warp 0) ----
    if (t < 32) {
        int d = t & 15;
        float x = 0.f;
#pragma unroll
        for (int w = 0; w < EW; w++) x += swacc[w * 17 + d];
        float mu = warp_sum16(x) * (1.f/16.f);
        float dl = x - mu;
        float var = warp_sum16(dl * dl) * (1.f/16.f);
        if (t < 16)
            out[c * (H_*D_) + h * D_ + d] =
                fmaf(dl * rsqrtf(var + EPS), out_gamma[d], out_beta[d]);
    }

    if (write_uid && h == 0 && t == 0)
        uid_out[c] = (float)c;
}

// ---------------------------------------------------------------------------
extern "C" void kernel_launch(void* const* d_in, const int* in_sizes, int n_in,
                              void* d_out, int out_size) {
    const float* feat      = (const float*)d_in[0];
    const float* query     = (const float*)d_in[1];
    const float* kw0       = (const float*)d_in[2];
    const float* kb0       = (const float*)d_in[3];
    const float* kw1       = (const float*)d_in[4];
    const float* kb1       = (const float*)d_in[5];
    const float* vw0       = (const float*)d_in[6];
    const float* vb0       = (const float*)d_in[7];
    const float* vw1       = (const float*)d_in[8];
    const float* vb1       = (const float*)d_in[9];
    const float* key_gamma = (const float*)d_in[10];
    const float* key_beta  = (const float*)d_in[11];
    const float* out_gamma = (const float*)d_in[12];
    const float* out_beta  = (const float*)d_in[13];
    const int*   comp      = (const int*)  d_in[14];   // int32 or int64; detected on device

    float* out = (float*)d_out;

    const int SZ_OUT  = C_ * H_ * D_;      // 2048
    const int SZ_ATTN = C_ * NLH;          // 524288
    const int full_attn = (out_size >= SZ_OUT + SZ_ATTN) ? 1 : 0;
    const int full_uid  = (out_size >= SZ_OUT + SZ_ATTN + C_) ? 1 : 0;

    float* attn_base;
    if (full_attn) {
        attn_base = out + SZ_OUT;
    } else {
        void* p = nullptr;
        cudaGetSymbolAddress(&p, g_attn_scratch);
        attn_base = (float*)p;
    }
    // d_out is poisoned before timing; zero the (sparse) attn region.
    cudaMemsetAsync(attn_base, 0, (size_t)SZ_ATTN * sizeof(float), 0);

    ffn_kernel<<<2 * N_ * L_, 128>>>(feat, query, kw0, kb0, kw1, kb1,
                                     vw0, vb0, vw1, vb1, key_gamma, key_beta,
                                     comp);

    float* uid_out = full_uid ? (out + SZ_OUT + SZ_ATTN) : (float*)nullptr;
    epilogue_kernel<<<C_ * H_, ET>>>(out_gamma, out_beta,
                                     attn_base, out, uid_out, full_uid);
}